// round 16
// baseline (speedup 1.0000x reference)
#include <cuda_runtime.h>
#include <cuda_fp16.h>

// EA-LSTM fused persistent kernel, round 15: 4-way k-split at 1024 threads
// (8 warps/SMSP) to break the latency/convoy wall, + fp16 single-stream
// weights (R14), + update distributed over 2 of 4 groups to fit 64 regs.
// B=1024, T=365, Dd=32, Ds=27, H=256, 3H=768, O=1.
//
// 128 CTAs x 1024 threads, M=8 batch elems per CTA. Group g = tid>>8 covers
// unified k in [72g, 72g+72) for all 3 gates of its column (fp16 weights,
// ONE LDG.64 per warp-k; fp32 f32x2 accumulation — only weights rounded).
// Roles after phase A: grp0 combines+updates m0..3, grp1 m4..7 (c/ig in
// registers, 4 each); grp2 stages x(t+1); grp3 computes the output dot.
// Groups publish only the partials the updaters need (36 u64 slots).

#define B_      1024
#define T_      365
#define DD      32
#define DS      27
#define H_      256
#define G3      768
#define M_      8
#define KTOT    288            // 32 x-k + 256 h-k (unified)
#define KG      72             // k per group
#define THREADS 1024
#define CTAS    (B_ / M_)      // 128
#define PSTRIDE 257            // padded u64 stride for partials
#define HT_S    264

typedef unsigned long long u64;

// fp16 packed weights, unified k axis (k<32 -> W_ih row k, else W_hh row k-32)
// .x = {wf, wo} half2 bits, .y = {wg, 0} half2 bits
__device__ uint2 WP[KTOT][256];

__device__ __forceinline__ u64 pack2(float lo, float hi) {
    u64 r; asm("mov.b64 %0, {%1, %2};" : "=l"(r) : "f"(lo), "f"(hi)); return r;
}
__device__ __forceinline__ void unpack2(u64 v, float& lo, float& hi) {
    asm("mov.b64 {%0, %1}, %2;" : "=f"(lo), "=f"(hi) : "l"(v));
}
__device__ __forceinline__ void fma2(u64& d, u64 a, u64 b) {
    asm("fma.rn.f32x2 %0, %1, %2, %0;" : "+l"(d) : "l"(a), "l"(b));
}
__device__ __forceinline__ void add2(u64& d, u64 a) {
    asm("add.rn.f32x2 %0, %0, %1;" : "+l"(d) : "l"(a));
}
__device__ __forceinline__ float sigmoidf_(float x) {
    return __fdividef(1.0f, 1.0f + __expf(-x));
}
__device__ __forceinline__ float tanhf_(float x) {
    float e = __expf(-2.0f * x);
    return __fdividef(1.0f - e, 1.0f + e);
}

__global__ void __launch_bounds__(256)
repack_kernel(const float* __restrict__ Wih, const float* __restrict__ Whh) {
    const int k   = blockIdx.x;        // unified k: 0..287
    const int col = threadIdx.x;       // 0..255
    const float* s = (k < DD) ? (Wih + k * G3) : (Whh + (k - DD) * G3);
    __half2 w01 = __floats2half2_rn(s[col], s[256 + col]);      // (wf, wo)
    __half2 w2  = __floats2half2_rn(s[512 + col], 0.0f);        // (wg, 0)
    uint2 p;
    p.x = *reinterpret_cast<unsigned int*>(&w01);
    p.y = *reinterpret_cast<unsigned int*>(&w2);
    WP[k][col] = p;
}

// dynamic SMEM: pub[36][PSTRIDE] u64 then xh[KTOT*M_] float
#define PUB_SLOTS  36
#define PUB_BYTES  (PUB_SLOTS * PSTRIDE * 8)          // 74016
#define XH_BYTES   (KTOT * M_ * 4)                    // 9216
#define DSM_BYTES  (PUB_BYTES + XH_BYTES)             // 83232

__global__ void __launch_bounds__(THREADS, 1)
ealstm_kernel(const float* __restrict__ xd,      // [B, T, DD]
              const float* __restrict__ xs,      // [B, DS]
              const float* __restrict__ Wsh,     // [DS, H]
              const float* __restrict__ bias,    // [3H]
              const float* __restrict__ bias_s,  // [H]
              const float* __restrict__ Wout,    // [H, 1]
              const float* __restrict__ bout,    // [1]
              float* __restrict__ out)           // [B, T, 1]
{
    __shared__ float h_t[M_][HT_S];                // h transposed for out-dot
    extern __shared__ __align__(16) unsigned char dsm[];
    u64*   pub = (u64*)dsm;                        // [36][PSTRIDE]
    float* xh  = (float*)(dsm + PUB_BYTES);        // k<32: x_t, else h (stride 8)

    const int tid  = threadIdx.x;
    const int grp  = tid >> 8;              // 0..3
    const int col  = tid & 255;
    const int b0   = blockIdx.x * M_;
    const int lane = tid & 31;
    const int warp = tid >> 5;
    const int k0   = grp * KG;

    // zero h region of xh
    for (int i = DD * M_ + tid; i < KTOT * M_; i += THREADS) xh[i] = 0.0f;

    // grp2 stages x_t for t = 0
    if (grp == 2) {
        const int m = col >> 5, k = col & 31;
        xh[k * M_ + m] = xd[((size_t)(b0 + m) * T_ + 0) * DD + k];
    }

    // grp0 seeds gate biases (carried through its accumulators for ALL pairs)
    float bf = 0.0f, bo = 0.0f, bg = 0.0f;
    if (grp == 0) { bf = bias[col]; bo = bias[H_ + col]; bg = bias[2 * H_ + col]; }

    // updaters (grp0: m0..3, grp1: m4..7): c + entity-aware input gate
    float c[4], ig[4];
    if (grp < 2) {
        float s[4];
        const float bs = bias_s[col];
        #pragma unroll
        for (int i = 0; i < 4; i++) { s[i] = bs; c[i] = 0.0f; }
        #pragma unroll 1
        for (int k = 0; k < DS; k++) {
            const float w = Wsh[k * H_ + col];
            #pragma unroll
            for (int i = 0; i < 4; i++)
                s[i] = fmaf(xs[(b0 + 4 * grp + i) * DS + k], w, s[i]);
        }
        #pragma unroll
        for (int i = 0; i < 4; i++) ig[i] = sigmoidf_(s[i]);
    }

    // grp3: out-dot weights (warp w-24 owns batch elem m=w-24)
    float wout[8];
    float b_out0 = 0.0f;
    if (grp == 3) {
        #pragma unroll
        for (int q = 0; q < 8; q++) wout[q] = Wout[lane + 32 * q];
        b_out0 = bout[0];
    }

    __syncthreads();

    for (int t = 0; t < T_; t++) {
        // ---- phase A: partial gate sums over this group's 72 k's ----
        u64 aF[4], aO[4], aG[4];
        if (grp == 0) {
            const u64 bf2 = pack2(bf, bf), bo2 = pack2(bo, bo), bg2 = pack2(bg, bg);
            #pragma unroll
            for (int p = 0; p < 4; p++) { aF[p] = bf2; aO[p] = bo2; aG[p] = bg2; }
        } else {
            #pragma unroll
            for (int p = 0; p < 4; p++) { aF[p] = 0ull; aO[p] = 0ull; aG[p] = 0ull; }
        }

        {
            const uint2* wp = &WP[k0][col];
            const float* hb = xh + k0 * M_;
            #pragma unroll 4
            for (int k = 0; k < KG; k++) {
                const uint2 wbits = __ldcg(wp + k * 256);       // ONE LDG.64
                const __half2 w01 = *reinterpret_cast<const __half2*>(&wbits.x);
                const float2 f01  = __half22float2(w01);        // (wf, wo)
                const float  fg   = __half2float(
                    *reinterpret_cast<const __half*>(&wbits.y));
                const u64 wf2 = pack2(f01.x, f01.x);
                const u64 wo2 = pack2(f01.y, f01.y);
                const u64 wg2 = pack2(fg, fg);
                const ulonglong2 hA = *(const ulonglong2*)(hb + k * M_);
                const ulonglong2 hB = *(const ulonglong2*)(hb + k * M_ + 4);
                fma2(aF[0], wf2, hA.x); fma2(aF[1], wf2, hA.y);
                fma2(aF[2], wf2, hB.x); fma2(aF[3], wf2, hB.y);
                fma2(aO[0], wo2, hA.x); fma2(aO[1], wo2, hA.y);
                fma2(aO[2], wo2, hB.x); fma2(aO[3], wo2, hB.y);
                fma2(aG[0], wg2, hA.x); fma2(aG[1], wg2, hA.y);
                fma2(aG[2], wg2, hB.x); fma2(aG[3], wg2, hB.y);
            }
        }

        // ---- publish the partials the updaters need ----
        // slots 0-5:  grp0 -> F2,F3,O2,O3,G2,G3   (for grp1)
        // slots 6-11: grp1 -> F0,F1,O0,O1,G0,G1   (for grp0)
        // slots 12-23: grp2 -> p0,p1 then p2,p3
        // slots 24-35: grp3 -> p0,p1 then p2,p3
        if (grp == 0) {
            pub[(0) * PSTRIDE + col] = aF[2];  pub[(1) * PSTRIDE + col] = aF[3];
            pub[(2) * PSTRIDE + col] = aO[2];  pub[(3) * PSTRIDE + col] = aO[3];
            pub[(4) * PSTRIDE + col] = aG[2];  pub[(5) * PSTRIDE + col] = aG[3];
        } else if (grp == 1) {
            pub[(6) * PSTRIDE + col] = aF[0];  pub[(7) * PSTRIDE + col] = aF[1];
            pub[(8) * PSTRIDE + col] = aO[0];  pub[(9) * PSTRIDE + col] = aO[1];
            pub[(10) * PSTRIDE + col] = aG[0]; pub[(11) * PSTRIDE + col] = aG[1];
        } else {
            const int s0 = (grp == 2) ? 12 : 24;
            pub[(s0 + 0) * PSTRIDE + col] = aF[0];
            pub[(s0 + 1) * PSTRIDE + col] = aF[1];
            pub[(s0 + 2) * PSTRIDE + col] = aO[0];
            pub[(s0 + 3) * PSTRIDE + col] = aO[1];
            pub[(s0 + 4) * PSTRIDE + col] = aG[0];
            pub[(s0 + 5) * PSTRIDE + col] = aG[1];
            pub[(s0 + 6) * PSTRIDE + col] = aF[2];
            pub[(s0 + 7) * PSTRIDE + col] = aF[3];
            pub[(s0 + 8) * PSTRIDE + col] = aO[2];
            pub[(s0 + 9) * PSTRIDE + col] = aO[3];
            pub[(s0 + 10) * PSTRIDE + col] = aG[2];
            pub[(s0 + 11) * PSTRIDE + col] = aG[3];
        }

        __syncthreads();   // BAR1: partials exchanged; xh reads of step t done

        if (grp == 0) {
            // combine + update m0..3 (pairs 0,1)
            float hn[4];
            #pragma unroll
            for (int p = 0; p < 2; p++) {
                u64 tF = aF[p], tO = aO[p], tG = aG[p];
                add2(tF, pub[(6 + p) * PSTRIDE + col]);
                add2(tF, pub[(12 + p) * PSTRIDE + col]);
                add2(tF, pub[(24 + p) * PSTRIDE + col]);
                add2(tO, pub[(8 + p) * PSTRIDE + col]);
                add2(tO, pub[(14 + p) * PSTRIDE + col]);
                add2(tO, pub[(26 + p) * PSTRIDE + col]);
                add2(tG, pub[(10 + p) * PSTRIDE + col]);
                add2(tG, pub[(16 + p) * PSTRIDE + col]);
                add2(tG, pub[(28 + p) * PSTRIDE + col]);
                float f0, f1, o0, o1, g0, g1;
                unpack2(tF, f0, f1); unpack2(tO, o0, o1); unpack2(tG, g0, g1);
                const int i0 = 2 * p, i1 = 2 * p + 1;
                c[i0] = sigmoidf_(f0) * c[i0] + ig[i0] * tanhf_(g0);
                c[i1] = sigmoidf_(f1) * c[i1] + ig[i1] * tanhf_(g1);
                hn[i0] = sigmoidf_(o0) * tanhf_(c[i0]);
                hn[i1] = sigmoidf_(o1) * tanhf_(c[i1]);
            }
            *(float4*)(xh + (DD + col) * M_) =
                make_float4(hn[0], hn[1], hn[2], hn[3]);
            h_t[0][col] = hn[0]; h_t[1][col] = hn[1];
            h_t[2][col] = hn[2]; h_t[3][col] = hn[3];
        } else if (grp == 1) {
            // combine + update m4..7 (pairs 2,3)
            float hn[4];
            #pragma unroll
            for (int p = 2; p < 4; p++) {
                const int i = p - 2;
                u64 tF = aF[p], tO = aO[p], tG = aG[p];
                add2(tF, pub[(0 + i) * PSTRIDE + col]);
                add2(tF, pub[(18 + i) * PSTRIDE + col]);
                add2(tF, pub[(30 + i) * PSTRIDE + col]);
                add2(tO, pub[(2 + i) * PSTRIDE + col]);
                add2(tO, pub[(20 + i) * PSTRIDE + col]);
                add2(tO, pub[(32 + i) * PSTRIDE + col]);
                add2(tG, pub[(4 + i) * PSTRIDE + col]);
                add2(tG, pub[(22 + i) * PSTRIDE + col]);
                add2(tG, pub[(34 + i) * PSTRIDE + col]);
                float f0, f1, o0, o1, g0, g1;
                unpack2(tF, f0, f1); unpack2(tO, o0, o1); unpack2(tG, g0, g1);
                const int i0 = 2 * i, i1 = 2 * i + 1;
                c[i0] = sigmoidf_(f0) * c[i0] + ig[i0] * tanhf_(g0);
                c[i1] = sigmoidf_(f1) * c[i1] + ig[i1] * tanhf_(g1);
                hn[i0] = sigmoidf_(o0) * tanhf_(c[i0]);
                hn[i1] = sigmoidf_(o1) * tanhf_(c[i1]);
            }
            *(float4*)(xh + (DD + col) * M_ + 4) =
                make_float4(hn[0], hn[1], hn[2], hn[3]);
            h_t[4][col] = hn[0]; h_t[5][col] = hn[1];
            h_t[6][col] = hn[2]; h_t[7][col] = hn[3];
        } else if (grp == 2) {
            // stage x for t+1 (x region: disjoint from h region)
            if (t + 1 < T_) {
                const int m = col >> 5, k = col & 31;
                xh[k * M_ + m] = xd[((size_t)(b0 + m) * T_ + (t + 1)) * DD + k];
            }
        }

        __syncthreads();   // BAR2: h(t), h_t(t), x(t+1) published

        // out-dot (grp3, warp w-24 = batch elem m). h_t stable until BAR1(t+1),
        // which grp3 reaches only after this — race-free.
        if (grp == 3) {
            const int w = warp - 24;
            float a = 0.0f;
            #pragma unroll
            for (int q = 0; q < 8; q++)
                a = fmaf(h_t[w][lane + 32 * q], wout[q], a);
            #pragma unroll
            for (int off = 16; off > 0; off >>= 1)
                a += __shfl_down_sync(0xffffffffu, a, off);
            if (lane == 0)
                out[(size_t)(b0 + w) * T_ + t] = a + b_out0;
        }
    }
}

extern "C" void kernel_launch(void* const* d_in, const int* in_sizes, int n_in,
                              void* d_out, int out_size) {
    const float* xd     = (const float*)d_in[0];  // x_dynamic [1024,365,32]
    const float* xs     = (const float*)d_in[1];  // x_static  [1024,27]
    const float* Wih    = (const float*)d_in[2];  // [32,768]
    const float* Whh    = (const float*)d_in[3];  // [256,768]
    const float* Wsh    = (const float*)d_in[4];  // [27,256]
    const float* bias   = (const float*)d_in[5];  // [768]
    const float* bias_s = (const float*)d_in[6];  // [256]
    const float* Wout   = (const float*)d_in[7];  // [256,1]
    const float* bout   = (const float*)d_in[8];  // [1]
    float* out = (float*)d_out;                   // [1024,365,1]

    (void)cudaFuncSetAttribute(ealstm_kernel,
                               cudaFuncAttributeMaxDynamicSharedMemorySize,
                               DSM_BYTES);
    (void)cudaGetLastError();

    repack_kernel<<<KTOT, 256>>>(Wih, Whh);
    ealstm_kernel<<<CTAS, THREADS, DSM_BYTES>>>(xd, xs, Wsh, bias, bias_s,
                                                Wout, bout, out);
}

// round 17
// speedup vs baseline: 1.1296x; 1.1296x over previous
#include <cuda_runtime.h>
#include <cuda_fp16.h>

// EA-LSTM fused persistent kernel, round 16: R14 base (split-k 512 thr, fp16
// single-stream weights, 4636us) + CROSS-BARRIER WEIGHT PREFETCH.
// Weights are t-invariant, so each thread re-arms its first PF weight loads
// for the NEXT step at the end of phase A; the loads fly across BAR1 +
// update + BAR2 and eliminate the post-barrier L2 latency ramp where all
// warps previously stalled together with nothing in flight.
// B=1024, T=365, Dd=32, Ds=27, H=256, 3H=768, O=1.
// Grid: 128 CTAs x 512 threads, M=8 batch elems per CTA. Thread (grp,col):
//   grp 0: bias + unified k in [0,144), grp 1: k in [144,288) -> partials.
// grp 0 combines + state update; grp 1 stages x(t+1) and does the out-dot.
// fp32 f32x2 accumulation; only weights rounded to fp16 (rel_err ~2.5e-4).

#define B_      1024
#define T_      365
#define DD      32
#define DS      27
#define H_      256
#define G3      768
#define M_      8
#define KTOT    288            // 32 x-k + 256 h-k (unified)
#define KG      144            // k per group
#define THREADS 512
#define CTAS    (B_ / M_)      // 128
#define PS_STRIDE 13           // padded partial stride (u64 per column)
#define HT_S    264
#define PF      6              // prefetch depth (uint2 regs held across barriers)

typedef unsigned long long u64;

// fp16 packed weights, unified k axis (k<32 -> W_ih row k, else W_hh row k-32)
// .x = {wf, wo} half2 bits, .y = {wg, 0} half2 bits
__device__ uint2 WP[KTOT][256];

__device__ __forceinline__ u64 pack2(float lo, float hi) {
    u64 r; asm("mov.b64 %0, {%1, %2};" : "=l"(r) : "f"(lo), "f"(hi)); return r;
}
__device__ __forceinline__ void unpack2(u64 v, float& lo, float& hi) {
    asm("mov.b64 {%0, %1}, %2;" : "=f"(lo), "=f"(hi) : "l"(v));
}
__device__ __forceinline__ void fma2(u64& d, u64 a, u64 b) {
    asm("fma.rn.f32x2 %0, %1, %2, %0;" : "+l"(d) : "l"(a), "l"(b));
}
__device__ __forceinline__ void add2(u64& d, u64 a) {
    asm("add.rn.f32x2 %0, %0, %1;" : "+l"(d) : "l"(a));
}
__device__ __forceinline__ float sigmoidf_(float x) {
    return __fdividef(1.0f, 1.0f + __expf(-x));
}
__device__ __forceinline__ float tanhf_(float x) {
    float e = __expf(-2.0f * x);
    return __fdividef(1.0f - e, 1.0f + e);
}

__global__ void __launch_bounds__(256)
repack_kernel(const float* __restrict__ Wih, const float* __restrict__ Whh) {
    const int k   = blockIdx.x;        // unified k: 0..287
    const int col = threadIdx.x;       // 0..255
    const float* s = (k < DD) ? (Wih + k * G3) : (Whh + (k - DD) * G3);
    __half2 w01 = __floats2half2_rn(s[col], s[256 + col]);      // (wf, wo)
    __half2 w2  = __floats2half2_rn(s[512 + col], 0.0f);        // (wg, 0)
    uint2 p;
    p.x = *reinterpret_cast<unsigned int*>(&w01);
    p.y = *reinterpret_cast<unsigned int*>(&w2);
    WP[k][col] = p;
}

// process one k: weights from bits, operands from xh
#define PROC_K(WBITS, HB)                                                     \
    do {                                                                      \
        const __half2 _w01 = *reinterpret_cast<const __half2*>(&(WBITS).x);   \
        const float2 _f01  = __half22float2(_w01);                            \
        const float  _fg   = __half2float(                                    \
            *reinterpret_cast<const __half*>(&(WBITS).y));                    \
        const u64 _wf2 = pack2(_f01.x, _f01.x);                               \
        const u64 _wo2 = pack2(_f01.y, _f01.y);                               \
        const u64 _wg2 = pack2(_fg, _fg);                                     \
        const ulonglong2 _hA = *(const ulonglong2*)(HB);                      \
        const ulonglong2 _hB = *(const ulonglong2*)((HB) + 4);                \
        fma2(aF[0], _wf2, _hA.x); fma2(aF[1], _wf2, _hA.y);                   \
        fma2(aF[2], _wf2, _hB.x); fma2(aF[3], _wf2, _hB.y);                   \
        fma2(aO[0], _wo2, _hA.x); fma2(aO[1], _wo2, _hA.y);                   \
        fma2(aO[2], _wo2, _hB.x); fma2(aO[3], _wo2, _hB.y);                   \
        fma2(aG[0], _wg2, _hA.x); fma2(aG[1], _wg2, _hA.y);                   \
        fma2(aG[2], _wg2, _hB.x); fma2(aG[3], _wg2, _hB.y);                   \
    } while (0)

__global__ void __launch_bounds__(THREADS, 1)
ealstm_kernel(const float* __restrict__ xd,      // [B, T, DD]
              const float* __restrict__ xs,      // [B, DS]
              const float* __restrict__ Wsh,     // [DS, H]
              const float* __restrict__ bias,    // [3H]
              const float* __restrict__ bias_s,  // [H]
              const float* __restrict__ Wout,    // [H, 1]
              const float* __restrict__ bout,    // [1]
              float* __restrict__ out)           // [B, T, 1]
{
    __shared__ __align__(16) float xh[KTOT * M_];  // k<32: x_t, else h (stride 8)
    __shared__ float h_t[M_][HT_S];                // h transposed for out-dot
    __shared__ u64   p_s[H_ * PS_STRIDE];          // group-1 partial gate sums

    const int j    = threadIdx.x;
    const int grp  = j >> 8;                // 0 or 1
    const int col  = j & 255;               // gate/h column
    const int b0   = blockIdx.x * M_;
    const int lane = j & 31;
    const int warp = j >> 5;
    const int k0   = grp * KG;              // unified k range start

    // zero h region of xh (indices [DD*M_, KTOT*M_))
    for (int idx = DD * M_ + j; idx < KTOT * M_; idx += THREADS) xh[idx] = 0.0f;

    // stage x_t for t = 0 (group 1's 256 threads)
    if (grp == 1) {
        const int m = col >> 5, k = col & 31;
        xh[k * M_ + m] = xd[((size_t)(b0 + m) * T_ + 0) * DD + k];
    }

    // per-thread gate biases (group 0 seeds accumulators)
    float bf = 0.0f, bo = 0.0f, bg = 0.0f;
    if (grp == 0) { bf = bias[col]; bo = bias[H_ + col]; bg = bias[2 * H_ + col]; }

    // entity-aware input gate (group 0 only)
    float ig[M_];
    if (grp == 0) {
        float s[M_];
        #pragma unroll
        for (int m = 0; m < M_; m++) s[m] = bias_s[col];
        #pragma unroll 1
        for (int k = 0; k < DS; k++) {
            const float w = Wsh[k * H_ + col];
            #pragma unroll
            for (int m = 0; m < M_; m++)
                s[m] = fmaf(xs[(b0 + m) * DS + k], w, s[m]);
        }
        #pragma unroll
        for (int m = 0; m < M_; m++) ig[m] = sigmoidf_(s[m]);
    }

    // per-lane output weights for the warp-level out-dot
    float wout[8];
    #pragma unroll
    for (int q = 0; q < 8; q++) wout[q] = Wout[lane + 32 * q];
    const float b_out0 = bout[0];

    float c[M_];
    #pragma unroll
    for (int m = 0; m < M_; m++) c[m] = 0.0f;

    // arm the prefetch for step 0
    const uint2* wp = &WP[k0][col];
    uint2 wpre[PF];
    #pragma unroll
    for (int q = 0; q < PF; q++) wpre[q] = __ldcg(wp + q * 256);

    __syncthreads();

    for (int t = 0; t < T_; t++) {
        u64 aF[4], aO[4], aG[4];
        if (grp == 0) {
            const u64 bf2 = pack2(bf, bf), bo2 = pack2(bo, bo), bg2 = pack2(bg, bg);
            #pragma unroll
            for (int p = 0; p < 4; p++) { aF[p] = bf2; aO[p] = bo2; aG[p] = bg2; }
        } else {
            #pragma unroll
            for (int p = 0; p < 4; p++) { aF[p] = 0ull; aO[p] = 0ull; aG[p] = 0ull; }
        }

        // ---- phase A: k in [0,PF) from prefetched regs, rest streamed ----
        {
            const float* hb = xh + k0 * M_;
            #pragma unroll
            for (int k = 0; k < PF; k++)
                PROC_K(wpre[k], hb + k * M_);
            #pragma unroll 4
            for (int k = PF; k < KG; k++) {
                const uint2 wbits = __ldcg(wp + k * 256);       // ONE LDG.64
                PROC_K(wbits, hb + k * M_);
            }
            // re-arm prefetch for NEXT step: loads fly across BAR1+update+BAR2
            #pragma unroll
            for (int q = 0; q < PF; q++) wpre[q] = __ldcg(wp + q * 256);
        }

        // group 1 publishes partials (per-col contiguous layout)
        if (grp == 1) {
            u64* pp = p_s + col * PS_STRIDE;
            #pragma unroll
            for (int p = 0; p < 4; p++) {
                pp[p]     = aF[p];
                pp[4 + p] = aO[p];
                pp[8 + p] = aG[p];
            }
        }

        __syncthreads();   // partials published; xh reads of step t done

        if (grp == 0) {
            // combine partials + state update
            const u64* pp = p_s + col * PS_STRIDE;
            #pragma unroll
            for (int p = 0; p < 4; p++) {
                add2(aF[p], pp[p]);
                add2(aO[p], pp[4 + p]);
                add2(aG[p], pp[8 + p]);
            }
            float hn[M_];
            #pragma unroll
            for (int p = 0; p < 4; p++) {
                float f0, f1, o0, o1, g0, g1;
                unpack2(aF[p], f0, f1);
                unpack2(aO[p], o0, o1);
                unpack2(aG[p], g0, g1);
                const int m0 = 2 * p, m1 = 2 * p + 1;
                c[m0] = sigmoidf_(f0) * c[m0] + ig[m0] * tanhf_(g0);
                c[m1] = sigmoidf_(f1) * c[m1] + ig[m1] * tanhf_(g1);
                hn[m0] = sigmoidf_(o0) * tanhf_(c[m0]);
                hn[m1] = sigmoidf_(o1) * tanhf_(c[m1]);
            }
            // publish h into xh h-region (stride-8 aligned, vectorized)
            float* hd = xh + (DD + col) * M_;
            *(float4*)(hd)     = make_float4(hn[0], hn[1], hn[2], hn[3]);
            *(float4*)(hd + 4) = make_float4(hn[4], hn[5], hn[6], hn[7]);
            // transposed copy for the out-dot
            #pragma unroll
            for (int m = 0; m < M_; m++) h_t[m][col] = hn[m];
        } else {
            // stage x for t+1 (x region: disjoint from h region)
            if (t + 1 < T_) {
                const int m = col >> 5, k = col & 31;
                xh[k * M_ + m] = xd[((size_t)(b0 + m) * T_ + (t + 1)) * DD + k];
            }
        }

        __syncthreads();   // h(t), h_t(t), x(t+1) published

        // output dot: group-1 warps (8..15) own batch elems 0..7
        if (grp == 1) {
            const int w = warp - 8;   // 0..7 = batch element m
            float a = 0.0f;
            #pragma unroll
            for (int q = 0; q < 8; q++)
                a = fmaf(h_t[w][lane + 32 * q], wout[q], a);
            #pragma unroll
            for (int off = 16; off > 0; off >>= 1)
                a += __shfl_down_sync(0xffffffffu, a, off);
            if (lane == 0)
                out[(size_t)(b0 + w) * T_ + t] = a + b_out0;
        }
        // h_t isn't rewritten until after the next step's first sync, so this
        // post-sync read overlap is race-free.
    }
}

extern "C" void kernel_launch(void* const* d_in, const int* in_sizes, int n_in,
                              void* d_out, int out_size) {
    const float* xd     = (const float*)d_in[0];  // x_dynamic [1024,365,32]
    const float* xs     = (const float*)d_in[1];  // x_static  [1024,27]
    const float* Wih    = (const float*)d_in[2];  // [32,768]
    const float* Whh    = (const float*)d_in[3];  // [256,768]
    const float* Wsh    = (const float*)d_in[4];  // [27,256]
    const float* bias   = (const float*)d_in[5];  // [768]
    const float* bias_s = (const float*)d_in[6];  // [256]
    const float* Wout   = (const float*)d_in[7];  // [256,1]
    const float* bout   = (const float*)d_in[8];  // [1]
    float* out = (float*)d_out;                   // [1024,365,1]

    repack_kernel<<<KTOT, 256>>>(Wih, Whh);
    ealstm_kernel<<<CTAS, THREADS>>>(xd, xs, Wsh, bias, bias_s,
                                     Wout, bout, out);
}